// round 1
// baseline (speedup 1.0000x reference)
#include <cuda_runtime.h>
#include <math.h>

#define NNEU 4096
#define BATCH 256
#define NSTEPS 12
#define LEAKF 0.95f
#define EPSF 1e-5f
#define CONN_THRF 0.01f

// ---------------- scratch (device globals; no allocation allowed) ----------------
__device__ __align__(16) float g_h1[BATCH * 32 * 14 * 14];
__device__ __align__(16) float g_h2[BATCH * 64 * 7 * 7];
__device__ __align__(16) float g_init[BATCH * NNEU];
__device__ __align__(16) float g_effw[NNEU * NNEU];
__device__ __align__(16) float g_spikes[BATCH * NNEU];
__device__ __align__(16) float g_pot[BATCH * NNEU];
__device__ __align__(16) float g_total[BATCH * NNEU];

// ---------------- conv1 + bn + relu + maxpool2 (fused) ----------------
// x:[256,1,28,28] w:[32,1,3,3] -> g_h1:[256,32,14,14]
__global__ void conv1_kernel(const float* __restrict__ x, const float* __restrict__ w,
                             const float* __restrict__ cb,
                             const float* __restrict__ bg, const float* __restrict__ bb,
                             const float* __restrict__ bm, const float* __restrict__ bv) {
    int idx = blockIdx.x * blockDim.x + threadIdx.x;
    const int total = BATCH * 32 * 14 * 14;
    if (idx >= total) return;
    int px = idx % 14;
    int py = (idx / 14) % 14;
    int oc = (idx / 196) % 32;
    int b = idx / (196 * 32);

    const float* xin = x + b * 784;
    float wreg[9];
#pragma unroll
    for (int j = 0; j < 9; ++j) wreg[j] = w[oc * 9 + j];
    float inv = bg[oc] * rsqrtf(bv[oc] + EPSF);
    float shift = bb[oc] - bm[oc] * inv;
    float bias = cb[oc];

    float best = -1e30f;
#pragma unroll
    for (int sy = 0; sy < 2; ++sy) {
#pragma unroll
        for (int sx = 0; sx < 2; ++sx) {
            int y = py * 2 + sy;
            int xx = px * 2 + sx;
            float acc = bias;
#pragma unroll
            for (int dy = 0; dy < 3; ++dy) {
                int iy = y + dy - 1;
                if (iy < 0 || iy >= 28) continue;
#pragma unroll
                for (int dx = 0; dx < 3; ++dx) {
                    int ix = xx + dx - 1;
                    if (ix < 0 || ix >= 28) continue;
                    acc = fmaf(xin[iy * 28 + ix], wreg[dy * 3 + dx], acc);
                }
            }
            float v = acc * inv + shift;  // bn
            best = fmaxf(best, v);        // bn monotone here; relu applied after max below
        }
    }
    g_h1[idx] = fmaxf(best, 0.f);
}

// ---------------- conv2 + bn + relu + maxpool2 (fused) ----------------
// g_h1:[256,32,14,14] w:[64,32,3,3] -> g_h2:[256,64,7,7]
__global__ void conv2_kernel(const float* __restrict__ w, const float* __restrict__ cb,
                             const float* __restrict__ bg, const float* __restrict__ bb,
                             const float* __restrict__ bm, const float* __restrict__ bv) {
    __shared__ float sin[32][16][16];  // zero-padded input, 32 KB
    int b = blockIdx.x;
    int ocg = blockIdx.y;  // 4 groups of 16 output channels
    int tid = threadIdx.x;

    float* sflat = &sin[0][0][0];
    for (int i = tid; i < 32 * 256; i += 256) sflat[i] = 0.f;
    __syncthreads();
    const float* in = g_h1 + b * 32 * 196;
    for (int i = tid; i < 32 * 196; i += 256) {
        int c = i / 196;
        int rem = i % 196;
        int y = rem / 14;
        int xx = rem % 14;
        sin[c][y + 1][xx + 1] = in[i];
    }
    __syncthreads();

    for (int o = tid; o < 16 * 49; o += 256) {
        int ocl = o / 49;
        int oc = ocg * 16 + ocl;
        int pos = o % 49;
        int py = pos / 7, px = pos % 7;
        int ybase = py * 2, xbase = px * 2;
        float a00 = 0.f, a01 = 0.f, a10 = 0.f, a11 = 0.f;
        const float* wp = w + oc * 32 * 9;
        for (int ic = 0; ic < 32; ++ic) {
            float w9[9];
#pragma unroll
            for (int j = 0; j < 9; ++j) w9[j] = wp[ic * 9 + j];
#pragma unroll
            for (int dy = 0; dy < 3; ++dy) {
#pragma unroll
                for (int dx = 0; dx < 3; ++dx) {
                    float wv = w9[dy * 3 + dx];
                    a00 = fmaf(sin[ic][ybase + dy][xbase + dx], wv, a00);
                    a01 = fmaf(sin[ic][ybase + dy][xbase + dx + 1], wv, a01);
                    a10 = fmaf(sin[ic][ybase + dy + 1][xbase + dx], wv, a10);
                    a11 = fmaf(sin[ic][ybase + dy + 1][xbase + dx + 1], wv, a11);
                }
            }
        }
        float inv = bg[oc] * rsqrtf(bv[oc] + EPSF);
        float shift = bb[oc] - bm[oc] * inv;
        float bias = cb[oc];
        float v00 = fmaxf((a00 + bias) * inv + shift, 0.f);
        float v01 = fmaxf((a01 + bias) * inv + shift, 0.f);
        float v10 = fmaxf((a10 + bias) * inv + shift, 0.f);
        float v11 = fmaxf((a11 + bias) * inv + shift, 0.f);
        float m = fmaxf(fmaxf(v00, v01), fmaxf(v10, v11));
        // NCHW flatten: index = oc*49 + py*7 + px
        g_h2[b * 3136 + oc * 49 + pos] = m;
    }
}

// ---------------- generic NT GEMM: C[M,N] = A[M,K] * B[N,K]^T (+bias) ----------------
// BM=BN=64, BK=16, 256 threads, 4x4 register tile.
__global__ void gemm_nt_kernel(const float* __restrict__ A, const float* __restrict__ B,
                               const float* __restrict__ bias, float* __restrict__ C,
                               int M, int Nn, int K) {
    __shared__ float As[16][64];
    __shared__ float Bs[16][64];
    int bm = blockIdx.y * 64;
    int bn = blockIdx.x * 64;
    int tid = threadIdx.x;
    int tx = tid % 16;
    int ty = tid / 16;
    int lrow = tid / 4;        // 0..63
    int lk = (tid % 4) * 4;    // 0,4,8,12

    float acc[4][4];
#pragma unroll
    for (int i = 0; i < 4; ++i)
#pragma unroll
        for (int j = 0; j < 4; ++j) acc[i][j] = 0.f;

    const float* Ap = A + (size_t)(bm + lrow) * K + lk;
    const float* Bp = B + (size_t)(bn + lrow) * K + lk;

    for (int k0 = 0; k0 < K; k0 += 16) {
        float4 av = *(const float4*)(Ap + k0);
        float4 bv = *(const float4*)(Bp + k0);
        As[lk + 0][lrow] = av.x;
        As[lk + 1][lrow] = av.y;
        As[lk + 2][lrow] = av.z;
        As[lk + 3][lrow] = av.w;
        Bs[lk + 0][lrow] = bv.x;
        Bs[lk + 1][lrow] = bv.y;
        Bs[lk + 2][lrow] = bv.z;
        Bs[lk + 3][lrow] = bv.w;
        __syncthreads();
#pragma unroll
        for (int kk = 0; kk < 16; ++kk) {
            float4 a = *(const float4*)&As[kk][ty * 4];
            float4 bq = *(const float4*)&Bs[kk][tx * 4];
            acc[0][0] = fmaf(a.x, bq.x, acc[0][0]);
            acc[0][1] = fmaf(a.x, bq.y, acc[0][1]);
            acc[0][2] = fmaf(a.x, bq.z, acc[0][2]);
            acc[0][3] = fmaf(a.x, bq.w, acc[0][3]);
            acc[1][0] = fmaf(a.y, bq.x, acc[1][0]);
            acc[1][1] = fmaf(a.y, bq.y, acc[1][1]);
            acc[1][2] = fmaf(a.y, bq.z, acc[1][2]);
            acc[1][3] = fmaf(a.y, bq.w, acc[1][3]);
            acc[2][0] = fmaf(a.z, bq.x, acc[2][0]);
            acc[2][1] = fmaf(a.z, bq.y, acc[2][1]);
            acc[2][2] = fmaf(a.z, bq.z, acc[2][2]);
            acc[2][3] = fmaf(a.z, bq.w, acc[2][3]);
            acc[3][0] = fmaf(a.w, bq.x, acc[3][0]);
            acc[3][1] = fmaf(a.w, bq.y, acc[3][1]);
            acc[3][2] = fmaf(a.w, bq.z, acc[3][2]);
            acc[3][3] = fmaf(a.w, bq.w, acc[3][3]);
        }
        __syncthreads();
    }

    float bvals[4] = {0.f, 0.f, 0.f, 0.f};
    if (bias) {
#pragma unroll
        for (int j = 0; j < 4; ++j) bvals[j] = bias[bn + tx * 4 + j];
    }
#pragma unroll
    for (int i = 0; i < 4; ++i) {
        float4 out;
        out.x = acc[i][0] + bvals[0];
        out.y = acc[i][1] + bvals[1];
        out.z = acc[i][2] + bvals[2];
        out.w = acc[i][3] + bvals[3];
        *(float4*)(C + (size_t)(bm + ty * 4 + i) * Nn + bn + tx * 4) = out;
    }
}

// ---------------- mask rec_w -> eff_w ----------------
__global__ void mask_kernel(const float* __restrict__ rw) {
    int i = blockIdx.x * blockDim.x + threadIdx.x;
    const int n4 = NNEU * NNEU / 4;
    if (i >= n4) return;
    float4 v = ((const float4*)rw)[i];
    v.x = (fabsf(v.x) > CONN_THRF) ? v.x : 0.f;
    v.y = (fabsf(v.y) > CONN_THRF) ? v.y : 0.f;
    v.z = (fabsf(v.z) > CONN_THRF) ? v.z : 0.f;
    v.w = (fabsf(v.w) > CONN_THRF) ? v.w : 0.f;
    ((float4*)g_effw)[i] = v;
}

// ---------------- fused layernorm + PulseTGAU neuron step ----------------
// one block per batch row; 512 threads x 8 elements
__global__ void step_kernel(const float* __restrict__ total_in, int first,
                            const float* __restrict__ lg, const float* __restrict__ lb,
                            const float* __restrict__ intr, const float* __restrict__ thr) {
    __shared__ float red[16];
    int b = blockIdx.x;
    int tid = threadIdx.x;
    int lane = tid & 31;
    int wid = tid >> 5;

    const float* row = total_in + (size_t)b * NNEU;
    float vals[8];
#pragma unroll
    for (int j = 0; j < 8; ++j) vals[j] = row[tid + j * 512];

    // mean
    float s = 0.f;
#pragma unroll
    for (int j = 0; j < 8; ++j) s += vals[j];
#pragma unroll
    for (int o = 16; o > 0; o >>= 1) s += __shfl_down_sync(0xffffffffu, s, o);
    if (lane == 0) red[wid] = s;
    __syncthreads();
    if (wid == 0) {
        float t = (lane < 16) ? red[lane] : 0.f;
#pragma unroll
        for (int o = 8; o > 0; o >>= 1) t += __shfl_down_sync(0xffffffffu, t, o);
        if (lane == 0) red[0] = t;
    }
    __syncthreads();
    float mu = red[0] * (1.f / NNEU);
    __syncthreads();

    // variance
    float s2 = 0.f;
#pragma unroll
    for (int j = 0; j < 8; ++j) {
        float d = vals[j] - mu;
        s2 = fmaf(d, d, s2);
    }
#pragma unroll
    for (int o = 16; o > 0; o >>= 1) s2 += __shfl_down_sync(0xffffffffu, s2, o);
    if (lane == 0) red[wid] = s2;
    __syncthreads();
    if (wid == 0) {
        float t = (lane < 16) ? red[lane] : 0.f;
#pragma unroll
        for (int o = 8; o > 0; o >>= 1) t += __shfl_down_sync(0xffffffffu, t, o);
        if (lane == 0) red[0] = t;
    }
    __syncthreads();
    float var = red[0] * (1.f / NNEU);
    float rsig = rsqrtf(var + EPSF);

#pragma unroll
    for (int j = 0; j < 8; ++j) {
        int n = tid + j * 512;
        size_t gi = (size_t)b * NNEU + n;
        float t = (vals[j] - mu) * rsig * lg[n] + lb[n];
        float pot = first ? 0.f : g_pot[gi];
        pot = pot * LEAKF + t + intr[n];
        float gated = pot - thr[n];
        float spike;
        if (gated > 0.f) {
            spike = gated / (1.f + expf(-gated));  // silu
            pot = pot - gated;                     // soft reset to threshold
        } else {
            spike = 0.f;
        }
        g_spikes[gi] = spike;
        g_pot[gi] = pot;
    }
}

// ---------------- classifier: out[b,c] = spikes[b,:] . cls_w[c,:] + cls_b[c] ----------------
__global__ void cls_kernel(const float* __restrict__ cw, const float* __restrict__ cbias,
                           float* __restrict__ out) {
    int b = blockIdx.x;
    int wid = threadIdx.x / 32;  // 0..9
    int lane = threadIdx.x % 32;
    const float* sp = g_spikes + (size_t)b * NNEU;
    const float* wv = cw + (size_t)wid * NNEU;
    float s = 0.f;
    for (int k = lane; k < NNEU; k += 32) s = fmaf(sp[k], wv[k], s);
#pragma unroll
    for (int o = 16; o > 0; o >>= 1) s += __shfl_down_sync(0xffffffffu, s, o);
    if (lane == 0) out[b * 10 + wid] = s + cbias[wid];
}

// ---------------- launch ----------------
extern "C" void kernel_launch(void* const* d_in, const int* in_sizes, int n_in,
                              void* d_out, int out_size) {
    const float* x = (const float*)d_in[0];
    const float* conv1_w = (const float*)d_in[1];
    const float* conv1_b = (const float*)d_in[2];
    const float* bn1_g = (const float*)d_in[3];
    const float* bn1_b = (const float*)d_in[4];
    const float* bn1_m = (const float*)d_in[5];
    const float* bn1_v = (const float*)d_in[6];
    const float* conv2_w = (const float*)d_in[7];
    const float* conv2_b = (const float*)d_in[8];
    const float* bn2_g = (const float*)d_in[9];
    const float* bn2_b = (const float*)d_in[10];
    const float* bn2_m = (const float*)d_in[11];
    const float* bn2_v = (const float*)d_in[12];
    const float* fc_w = (const float*)d_in[13];
    const float* fc_b = (const float*)d_in[14];
    const float* rec_w = (const float*)d_in[15];
    const float* threshold = (const float*)d_in[16];
    const float* intrinsic = (const float*)d_in[17];
    const float* ln_g = (const float*)d_in[18];
    const float* ln_b = (const float*)d_in[19];
    const float* cls_w = (const float*)d_in[20];
    const float* cls_b = (const float*)d_in[21];
    float* out = (float*)d_out;

    void *p_h2, *p_init, *p_effw, *p_spikes, *p_total;
    cudaGetSymbolAddress(&p_h2, g_h2);
    cudaGetSymbolAddress(&p_init, g_init);
    cudaGetSymbolAddress(&p_effw, g_effw);
    cudaGetSymbolAddress(&p_spikes, g_spikes);
    cudaGetSymbolAddress(&p_total, g_total);

    // vision frontend
    {
        int tot = BATCH * 32 * 14 * 14;
        conv1_kernel<<<(tot + 255) / 256, 256>>>(x, conv1_w, conv1_b, bn1_g, bn1_b, bn1_m, bn1_v);
    }
    conv2_kernel<<<dim3(BATCH, 4), 256>>>(conv2_w, conv2_b, bn2_g, bn2_b, bn2_m, bn2_v);

    // FC: initial_current = h2 @ fc_w^T + fc_b   [256,4096], K=3136
    gemm_nt_kernel<<<dim3(NNEU / 64, BATCH / 64), 256>>>((const float*)p_h2, fc_w, fc_b,
                                                         (float*)p_init, BATCH, NNEU, 3136);

    // mask weights (also warms eff_w into L2)
    mask_kernel<<<(NNEU * NNEU / 4 + 255) / 256, 256>>>(rec_w);

    // step 0: spikes==0 -> total == initial_current (skip GEMM)
    step_kernel<<<BATCH, 512>>>((const float*)p_init, 1, ln_g, ln_b, intrinsic, threshold);

    // steps 1..11
    for (int s = 1; s < NSTEPS; ++s) {
        gemm_nt_kernel<<<dim3(NNEU / 64, BATCH / 64), 256>>>((const float*)p_spikes,
                                                             (const float*)p_effw, nullptr,
                                                             (float*)p_total, BATCH, NNEU, NNEU);
        step_kernel<<<BATCH, 512>>>((const float*)p_total, 0, ln_g, ln_b, intrinsic, threshold);
    }

    // classifier
    cls_kernel<<<BATCH, 320>>>(cls_w, cls_b, out);
}

// round 11
// speedup vs baseline: 4.9573x; 4.9573x over previous
#include <cuda_runtime.h>
#include <cuda_bf16.h>
#include <math.h>
#include <stdint.h>

#define NNEU 4096
#define BATCH 256
#define NSTEPS 12
#define LEAKF 0.95f
#define EPSF 1e-5f
#define CONN_THRF 0.01f
#define FCK 3136

// ---------------- gemm tiling (mma.sync path; compute_103-safe) ----------------
#define KCHUNK 64
#define STAGES 3
#define AS_STRIDE 72              // bf16 elems per smem row (64 data + 8 pad)
#define ROWB (AS_STRIDE * 2)      // 144 bytes; conflict-free for ldmatrix
#define A_ROWS 128
#define B_ROWS 64
#define AHI_OFF 0
#define ALO_OFF (A_ROWS * ROWB)                       // 18432
#define BHI_OFF (2 * A_ROWS * ROWB)                   // 36864
#define BLO_OFF (2 * A_ROWS * ROWB + B_ROWS * ROWB)   // 46080
#define STAGE_BYTES (2 * A_ROWS * ROWB + 2 * B_ROWS * ROWB)  // 55296
#define GEMM_THREADS 256
#define SMEM_DYN (STAGES * STAGE_BYTES)               // 165888

// ---------------- scratch (device globals; no allocation allowed) ----------------
__device__ __align__(16) float g_h1[BATCH * 32 * 14 * 14];
__device__ __align__(16) float g_h2[BATCH * FCK];
__device__ __align__(16) __nv_bfloat16 g_h2hi[BATCH * FCK];
__device__ __align__(16) __nv_bfloat16 g_h2lo[BATCH * FCK];
__device__ __align__(16) __nv_bfloat16 g_fwhi[NNEU * FCK];
__device__ __align__(16) __nv_bfloat16 g_fwlo[NNEU * FCK];
__device__ __align__(16) __nv_bfloat16 g_bhi[NNEU * NNEU];
__device__ __align__(16) __nv_bfloat16 g_blo[NNEU * NNEU];
__device__ __align__(16) float g_init[BATCH * NNEU];
__device__ __align__(16) float g_spikes[BATCH * NNEU];
__device__ __align__(16) __nv_bfloat16 g_ahi[BATCH * NNEU];
__device__ __align__(16) __nv_bfloat16 g_alo[BATCH * NNEU];
__device__ __align__(16) float g_pot[BATCH * NNEU];
__device__ __align__(16) float g_total[BATCH * NNEU];

// ---------------- ptx helpers ----------------
__device__ __forceinline__ uint32_t smem_u32(const void* p) {
    uint32_t a;
    asm("{ .reg .u64 t; cvta.to.shared.u64 t, %1; cvt.u32.u64 %0, t; }" : "=r"(a) : "l"(p));
    return a;
}

__device__ __forceinline__ void cpa16(uint32_t dst, const void* src) {
    asm volatile("cp.async.cg.shared.global [%0], [%1], 16;" ::"r"(dst), "l"(src) : "memory");
}

__device__ __forceinline__ void ldsm4(uint32_t* r, uint32_t addr) {
    asm volatile("ldmatrix.sync.aligned.m8n8.x4.shared.b16 {%0,%1,%2,%3}, [%4];"
                 : "=r"(r[0]), "=r"(r[1]), "=r"(r[2]), "=r"(r[3])
                 : "r"(addr));
}

__device__ __forceinline__ void mma16816(float* c, const uint32_t* a, const uint32_t* b) {
    asm volatile(
        "mma.sync.aligned.m16n8k16.row.col.f32.bf16.bf16.f32 "
        "{%0,%1,%2,%3}, {%4,%5,%6,%7}, {%8,%9}, {%0,%1,%2,%3};"
        : "+f"(c[0]), "+f"(c[1]), "+f"(c[2]), "+f"(c[3])
        : "r"(a[0]), "r"(a[1]), "r"(a[2]), "r"(a[3]), "r"(b[0]), "r"(b[1]));
}

// ---------------- split-bf16 HMMA GEMM ----------------
// C[256, 4096] = (Ahi+Alo)[256,K] x (Bhi+Blo)[4096,K]^T  (drops lo*lo term)
// CTA tile: M=128 (blockIdx.y in {0,1}), N=64 (blockIdx.x in 0..63)
// 8 warps = 4(M) x 2(N), warp tile 32x32, fp32 accum in registers.
__global__ void __launch_bounds__(GEMM_THREADS, 1) gemm_mma_kernel(
    const __nv_bfloat16* __restrict__ Ahi, const __nv_bfloat16* __restrict__ Alo,
    const __nv_bfloat16* __restrict__ Bhi, const __nv_bfloat16* __restrict__ Blo,
    const float* __restrict__ bias, float* __restrict__ C, int K) {
    extern __shared__ char dyn_smem[];
    const uint32_t sb = smem_u32(dyn_smem);
    const int tid = threadIdx.x;
    const int wid = tid >> 5;
    const int lane = tid & 31;
    const int wm = wid >> 1;  // 0..3
    const int wn = wid & 1;   // 0..1
    const int bm = blockIdx.y * 128;
    const int bn = blockIdx.x * 64;
    const int NKB = K / KCHUNK;

    // ---- stage loader: 3072 x 16B chunks / 256 threads = 12 each ----
    auto load_stage = [&](int stg, int kb) {
        const uint32_t base = sb + stg * STAGE_BYTES;
        const int k0 = kb * KCHUNK;
#pragma unroll
        for (int i = 0; i < 12; ++i) {
            int c = tid + i * GEMM_THREADS;
            const __nv_bfloat16* src;
            uint32_t dst;
            if (c < 2048) {  // A: 128 rows x 8 chunks, hi then lo
                int r = (c >> 3) & 127;
                int col = c & 7;
                src = ((c < 1024) ? Ahi : Alo) + (size_t)(bm + r) * K + k0 + col * 8;
                dst = base + ((c < 1024) ? AHI_OFF : ALO_OFF) + r * ROWB + col * 16;
            } else {  // B: 64 rows x 8 chunks, hi then lo
                int cc = c - 2048;
                int r = (cc >> 3) & 63;
                int col = cc & 7;
                src = ((cc < 512) ? Bhi : Blo) + (size_t)(bn + r) * K + k0 + col * 8;
                dst = base + ((cc < 512) ? BHI_OFF : BLO_OFF) + r * ROWB + col * 16;
            }
            cpa16(dst, src);
        }
    };

    // prologue: fill stages 0,1
    load_stage(0, 0);
    asm volatile("cp.async.commit_group;" ::: "memory");
    load_stage(1, 1);
    asm volatile("cp.async.commit_group;" ::: "memory");

    float acc[2][4][4];
#pragma unroll
    for (int mt = 0; mt < 2; ++mt)
#pragma unroll
        for (int nt = 0; nt < 4; ++nt)
#pragma unroll
            for (int e = 0; e < 4; ++e) acc[mt][nt][e] = 0.f;

    // per-thread ldmatrix address components
    const int q = lane >> 3;   // quadrant 0..3
    const int r8 = lane & 7;
    // A x4: q0:(m+r8,k) q1:(m+8+r8,k) q2:(m+r8,k+8) q3:(m+8+r8,k+8)
    const int a_row = wm * 32 + r8 + ((q & 1) << 3);
    const int a_kq = (q >> 1) << 3;
    // B x4: q0:(n+r8,k) q1:(n+r8,k+8) q2:(n+8+r8,k) q3:(n+8+r8,k+8)
    const int b_row = wn * 32 + r8 + ((q >> 1) << 3);
    const int b_kq = (q & 1) << 3;

    for (int kb = 0; kb < NKB; ++kb) {
        if (kb + 2 < NKB) load_stage((kb + 2) % 3, kb + 2);
        asm volatile("cp.async.commit_group;" ::: "memory");
        asm volatile("cp.async.wait_group 2;" ::: "memory");
        __syncthreads();

        const uint32_t base = sb + (kb % 3) * STAGE_BYTES;
#pragma unroll
        for (int ks = 0; ks < 4; ++ks) {
            const int kk = ks * 16;
            uint32_t ah[2][4], al[2][4], bh[2][4], bl[2][4];
#pragma unroll
            for (int mt = 0; mt < 2; ++mt) {
                uint32_t off = (a_row + mt * 16) * ROWB + (kk + a_kq) * 2;
                ldsm4(ah[mt], base + AHI_OFF + off);
                ldsm4(al[mt], base + ALO_OFF + off);
            }
#pragma unroll
            for (int p = 0; p < 2; ++p) {  // pair p covers n-tiles 2p, 2p+1
                uint32_t off = (b_row + p * 16) * ROWB + (kk + b_kq) * 2;
                ldsm4(bh[p], base + BHI_OFF + off);
                ldsm4(bl[p], base + BLO_OFF + off);
            }
#pragma unroll
            for (int mt = 0; mt < 2; ++mt)
#pragma unroll
                for (int p = 0; p < 2; ++p)
#pragma unroll
                    for (int sub = 0; sub < 2; ++sub) {
                        int nt = p * 2 + sub;
                        mma16816(acc[mt][nt], ah[mt], &bh[p][sub * 2]);  // hi*hi
                        mma16816(acc[mt][nt], al[mt], &bh[p][sub * 2]);  // lo*hi
                        mma16816(acc[mt][nt], ah[mt], &bl[p][sub * 2]);  // hi*lo
                    }
        }
        __syncthreads();
    }

    // ---- epilogue: c0,c1 at (m=g, n=2j,2j+1); c2,c3 at (m=g+8, ...) ----
    const int g = lane >> 2;
    const int j2 = (lane & 3) * 2;
#pragma unroll
    for (int mt = 0; mt < 2; ++mt) {
#pragma unroll
        for (int nt = 0; nt < 4; ++nt) {
            int row0 = bm + wm * 32 + mt * 16 + g;
            int col = bn + wn * 32 + nt * 8 + j2;
            float b0 = 0.f, b1 = 0.f;
            if (bias) {
                b0 = bias[col];
                b1 = bias[col + 1];
            }
            float2 v0, v1;
            v0.x = acc[mt][nt][0] + b0;
            v0.y = acc[mt][nt][1] + b1;
            v1.x = acc[mt][nt][2] + b0;
            v1.y = acc[mt][nt][3] + b1;
            *(float2*)(C + (size_t)row0 * NNEU + col) = v0;
            *(float2*)(C + (size_t)(row0 + 8) * NNEU + col) = v1;
        }
    }
}

// ---------------- conv1 + bn + relu + maxpool2 (fused) ----------------
__global__ void conv1_kernel(const float* __restrict__ x, const float* __restrict__ w,
                             const float* __restrict__ cb, const float* __restrict__ bg,
                             const float* __restrict__ bb, const float* __restrict__ bm,
                             const float* __restrict__ bv) {
    int idx = blockIdx.x * blockDim.x + threadIdx.x;
    const int total = BATCH * 32 * 14 * 14;
    if (idx >= total) return;
    int px = idx % 14;
    int py = (idx / 14) % 14;
    int oc = (idx / 196) % 32;
    int b = idx / (196 * 32);

    const float* xin = x + b * 784;
    float wreg[9];
#pragma unroll
    for (int j = 0; j < 9; ++j) wreg[j] = w[oc * 9 + j];
    float inv = bg[oc] * rsqrtf(bv[oc] + EPSF);
    float shift = bb[oc] - bm[oc] * inv;
    float bias = cb[oc];

    float best = -1e30f;
#pragma unroll
    for (int sy = 0; sy < 2; ++sy) {
#pragma unroll
        for (int sx = 0; sx < 2; ++sx) {
            int y = py * 2 + sy;
            int xx = px * 2 + sx;
            float acc = bias;
#pragma unroll
            for (int dy = 0; dy < 3; ++dy) {
                int iy = y + dy - 1;
                if (iy < 0 || iy >= 28) continue;
#pragma unroll
                for (int dx = 0; dx < 3; ++dx) {
                    int ix = xx + dx - 1;
                    if (ix < 0 || ix >= 28) continue;
                    acc = fmaf(xin[iy * 28 + ix], wreg[dy * 3 + dx], acc);
                }
            }
            float v = acc * inv + shift;
            best = fmaxf(best, v);
        }
    }
    g_h1[idx] = fmaxf(best, 0.f);
}

// ---------------- conv2 + bn + relu + maxpool2 (fused) ----------------
__global__ void conv2_kernel(const float* __restrict__ w, const float* __restrict__ cb,
                             const float* __restrict__ bg, const float* __restrict__ bb,
                             const float* __restrict__ bm, const float* __restrict__ bv) {
    __shared__ float sin[32][16][16];
    int b = blockIdx.x;
    int ocg = blockIdx.y;
    int tid = threadIdx.x;

    float* sflat = &sin[0][0][0];
    for (int i = tid; i < 32 * 256; i += 256) sflat[i] = 0.f;
    __syncthreads();
    const float* in = g_h1 + b * 32 * 196;
    for (int i = tid; i < 32 * 196; i += 256) {
        int c = i / 196;
        int rem = i % 196;
        int y = rem / 14;
        int xx = rem % 14;
        sin[c][y + 1][xx + 1] = in[i];
    }
    __syncthreads();

    for (int o = tid; o < 16 * 49; o += 256) {
        int ocl = o / 49;
        int oc = ocg * 16 + ocl;
        int pos = o % 49;
        int py = pos / 7, px = pos % 7;
        int ybase = py * 2, xbase = px * 2;
        float a00 = 0.f, a01 = 0.f, a10 = 0.f, a11 = 0.f;
        const float* wp = w + oc * 32 * 9;
        for (int ic = 0; ic < 32; ++ic) {
            float w9[9];
#pragma unroll
            for (int j = 0; j < 9; ++j) w9[j] = wp[ic * 9 + j];
#pragma unroll
            for (int dy = 0; dy < 3; ++dy) {
#pragma unroll
                for (int dx = 0; dx < 3; ++dx) {
                    float wv = w9[dy * 3 + dx];
                    a00 = fmaf(sin[ic][ybase + dy][xbase + dx], wv, a00);
                    a01 = fmaf(sin[ic][ybase + dy][xbase + dx + 1], wv, a01);
                    a10 = fmaf(sin[ic][ybase + dy + 1][xbase + dx], wv, a10);
                    a11 = fmaf(sin[ic][ybase + dy + 1][xbase + dx + 1], wv, a11);
                }
            }
        }
        float inv = bg[oc] * rsqrtf(bv[oc] + EPSF);
        float shift = bb[oc] - bm[oc] * inv;
        float bias = cb[oc];
        float v00 = fmaxf((a00 + bias) * inv + shift, 0.f);
        float v01 = fmaxf((a01 + bias) * inv + shift, 0.f);
        float v10 = fmaxf((a10 + bias) * inv + shift, 0.f);
        float v11 = fmaxf((a11 + bias) * inv + shift, 0.f);
        float m = fmaxf(fmaxf(v00, v01), fmaxf(v10, v11));
        g_h2[b * FCK + oc * 49 + pos] = m;
    }
}

// ---------------- fp32 -> bf16 hi/lo split (4-wide) ----------------
__global__ void split4_kernel(const float4* __restrict__ src, __nv_bfloat162* __restrict__ hi,
                              __nv_bfloat162* __restrict__ lo, int n4) {
    int i = blockIdx.x * blockDim.x + threadIdx.x;
    if (i >= n4) return;
    float4 v = src[i];
    __nv_bfloat16 h0 = __float2bfloat16(v.x), h1 = __float2bfloat16(v.y);
    __nv_bfloat16 h2 = __float2bfloat16(v.z), h3 = __float2bfloat16(v.w);
    __nv_bfloat162 ph0, ph1, pl0, pl1;
    ph0.x = h0; ph0.y = h1;
    ph1.x = h2; ph1.y = h3;
    pl0.x = __float2bfloat16(v.x - __bfloat162float(h0));
    pl0.y = __float2bfloat16(v.y - __bfloat162float(h1));
    pl1.x = __float2bfloat16(v.z - __bfloat162float(h2));
    pl1.y = __float2bfloat16(v.w - __bfloat162float(h3));
    hi[i * 2 + 0] = ph0;
    hi[i * 2 + 1] = ph1;
    lo[i * 2 + 0] = pl0;
    lo[i * 2 + 1] = pl1;
}

// ---------------- mask rec_w then split ----------------
__global__ void mask_split4_kernel(const float4* __restrict__ src) {
    int i = blockIdx.x * blockDim.x + threadIdx.x;
    const int n4 = NNEU * NNEU / 4;
    if (i >= n4) return;
    float4 v = src[i];
    v.x = (fabsf(v.x) > CONN_THRF) ? v.x : 0.f;
    v.y = (fabsf(v.y) > CONN_THRF) ? v.y : 0.f;
    v.z = (fabsf(v.z) > CONN_THRF) ? v.z : 0.f;
    v.w = (fabsf(v.w) > CONN_THRF) ? v.w : 0.f;
    __nv_bfloat16 h0 = __float2bfloat16(v.x), h1 = __float2bfloat16(v.y);
    __nv_bfloat16 h2 = __float2bfloat16(v.z), h3 = __float2bfloat16(v.w);
    __nv_bfloat162 ph0, ph1, pl0, pl1;
    ph0.x = h0; ph0.y = h1;
    ph1.x = h2; ph1.y = h3;
    pl0.x = __float2bfloat16(v.x - __bfloat162float(h0));
    pl0.y = __float2bfloat16(v.y - __bfloat162float(h1));
    pl1.x = __float2bfloat16(v.z - __bfloat162float(h2));
    pl1.y = __float2bfloat16(v.w - __bfloat162float(h3));
    ((__nv_bfloat162*)g_bhi)[i * 2 + 0] = ph0;
    ((__nv_bfloat162*)g_bhi)[i * 2 + 1] = ph1;
    ((__nv_bfloat162*)g_blo)[i * 2 + 0] = pl0;
    ((__nv_bfloat162*)g_blo)[i * 2 + 1] = pl1;
}

// ---------------- fused layernorm + PulseTGAU neuron step ----------------
__global__ void step_kernel(const float* __restrict__ total_in, int first,
                            const float* __restrict__ lg, const float* __restrict__ lb,
                            const float* __restrict__ intr, const float* __restrict__ thr) {
    __shared__ float red[16];
    int b = blockIdx.x;
    int tid = threadIdx.x;
    int lane = tid & 31;
    int wid = tid >> 5;

    const float* row = total_in + (size_t)b * NNEU;
    float vals[8];
#pragma unroll
    for (int j = 0; j < 8; ++j) vals[j] = row[tid + j * 512];

    float s = 0.f;
#pragma unroll
    for (int j = 0; j < 8; ++j) s += vals[j];
#pragma unroll
    for (int o = 16; o > 0; o >>= 1) s += __shfl_down_sync(0xffffffffu, s, o);
    if (lane == 0) red[wid] = s;
    __syncthreads();
    if (wid == 0) {
        float t = (lane < 16) ? red[lane] : 0.f;
#pragma unroll
        for (int o = 8; o > 0; o >>= 1) t += __shfl_down_sync(0xffffffffu, t, o);
        if (lane == 0) red[0] = t;
    }
    __syncthreads();
    float mu = red[0] * (1.f / NNEU);
    __syncthreads();

    float s2 = 0.f;
#pragma unroll
    for (int j = 0; j < 8; ++j) {
        float d = vals[j] - mu;
        s2 = fmaf(d, d, s2);
    }
#pragma unroll
    for (int o = 16; o > 0; o >>= 1) s2 += __shfl_down_sync(0xffffffffu, s2, o);
    if (lane == 0) red[wid] = s2;
    __syncthreads();
    if (wid == 0) {
        float t = (lane < 16) ? red[lane] : 0.f;
#pragma unroll
        for (int o = 8; o > 0; o >>= 1) t += __shfl_down_sync(0xffffffffu, t, o);
        if (lane == 0) red[0] = t;
    }
    __syncthreads();
    float var = red[0] * (1.f / NNEU);
    float rsig = rsqrtf(var + EPSF);

#pragma unroll
    for (int j = 0; j < 8; ++j) {
        int n = tid + j * 512;
        size_t gi = (size_t)b * NNEU + n;
        float t = (vals[j] - mu) * rsig * lg[n] + lb[n];
        float pot = first ? 0.f : g_pot[gi];
        pot = pot * LEAKF + t + intr[n];
        float gated = pot - thr[n];
        float spike;
        if (gated > 0.f) {
            spike = gated / (1.f + expf(-gated));
            pot = pot - gated;
        } else {
            spike = 0.f;
        }
        g_spikes[gi] = spike;
        __nv_bfloat16 h = __float2bfloat16(spike);
        g_ahi[gi] = h;
        g_alo[gi] = __float2bfloat16(spike - __bfloat162float(h));
        g_pot[gi] = pot;
    }
}

// ---------------- classifier ----------------
__global__ void cls_kernel(const float* __restrict__ cw, const float* __restrict__ cbias,
                           float* __restrict__ out) {
    int b = blockIdx.x;
    int wid = threadIdx.x / 32;
    int lane = threadIdx.x % 32;
    const float* sp = g_spikes + (size_t)b * NNEU;
    const float* wv = cw + (size_t)wid * NNEU;
    float s = 0.f;
    for (int k = lane; k < NNEU; k += 32) s = fmaf(sp[k], wv[k], s);
#pragma unroll
    for (int o = 16; o > 0; o >>= 1) s += __shfl_down_sync(0xffffffffu, s, o);
    if (lane == 0) out[b * 10 + wid] = s + cbias[wid];
}

// ---------------- launch ----------------
extern "C" void kernel_launch(void* const* d_in, const int* in_sizes, int n_in,
                              void* d_out, int out_size) {
    const float* x = (const float*)d_in[0];
    const float* conv1_w = (const float*)d_in[1];
    const float* conv1_b = (const float*)d_in[2];
    const float* bn1_g = (const float*)d_in[3];
    const float* bn1_b = (const float*)d_in[4];
    const float* bn1_m = (const float*)d_in[5];
    const float* bn1_v = (const float*)d_in[6];
    const float* conv2_w = (const float*)d_in[7];
    const float* conv2_b = (const float*)d_in[8];
    const float* bn2_g = (const float*)d_in[9];
    const float* bn2_b = (const float*)d_in[10];
    const float* bn2_m = (const float*)d_in[11];
    const float* bn2_v = (const float*)d_in[12];
    const float* fc_w = (const float*)d_in[13];
    const float* fc_b = (const float*)d_in[14];
    const float* rec_w = (const float*)d_in[15];
    const float* threshold = (const float*)d_in[16];
    const float* intrinsic = (const float*)d_in[17];
    const float* ln_g = (const float*)d_in[18];
    const float* ln_b = (const float*)d_in[19];
    const float* cls_w = (const float*)d_in[20];
    const float* cls_b = (const float*)d_in[21];
    float* out = (float*)d_out;

    void *p_h2, *p_h2hi, *p_h2lo, *p_fwhi, *p_fwlo, *p_bhi, *p_blo;
    void *p_init, *p_total, *p_ahi, *p_alo;
    cudaGetSymbolAddress(&p_h2, g_h2);
    cudaGetSymbolAddress(&p_h2hi, g_h2hi);
    cudaGetSymbolAddress(&p_h2lo, g_h2lo);
    cudaGetSymbolAddress(&p_fwhi, g_fwhi);
    cudaGetSymbolAddress(&p_fwlo, g_fwlo);
    cudaGetSymbolAddress(&p_bhi, g_bhi);
    cudaGetSymbolAddress(&p_blo, g_blo);
    cudaGetSymbolAddress(&p_init, g_init);
    cudaGetSymbolAddress(&p_total, g_total);
    cudaGetSymbolAddress(&p_ahi, g_ahi);
    cudaGetSymbolAddress(&p_alo, g_alo);

    cudaFuncSetAttribute(gemm_mma_kernel, cudaFuncAttributeMaxDynamicSharedMemorySize, SMEM_DYN);

    // vision frontend
    {
        int tot = BATCH * 32 * 14 * 14;
        conv1_kernel<<<(tot + 255) / 256, 256>>>(x, conv1_w, conv1_b, bn1_g, bn1_b, bn1_m, bn1_v);
    }
    conv2_kernel<<<dim3(BATCH, 4), 256>>>(conv2_w, conv2_b, bn2_g, bn2_b, bn2_m, bn2_v);

    // splits
    {
        int n4 = BATCH * FCK / 4;
        split4_kernel<<<(n4 + 255) / 256, 256>>>((const float4*)p_h2, (__nv_bfloat162*)p_h2hi,
                                                 (__nv_bfloat162*)p_h2lo, n4);
    }
    {
        int n4 = NNEU * FCK / 4;
        split4_kernel<<<(n4 + 255) / 256, 256>>>((const float4*)fc_w, (__nv_bfloat162*)p_fwhi,
                                                 (__nv_bfloat162*)p_fwlo, n4);
    }
    mask_split4_kernel<<<(NNEU * NNEU / 4 + 255) / 256, 256>>>((const float4*)rec_w);

    // FC: initial_current = h2 @ fc_w^T + fc_b   (K = 3136 = 49 * 64)
    gemm_mma_kernel<<<dim3(NNEU / 64, 2), GEMM_THREADS, SMEM_DYN>>>(
        (const __nv_bfloat16*)p_h2hi, (const __nv_bfloat16*)p_h2lo,
        (const __nv_bfloat16*)p_fwhi, (const __nv_bfloat16*)p_fwlo, fc_b, (float*)p_init, FCK);

    // step 0: spikes==0 -> total == initial_current (skip GEMM)
    step_kernel<<<BATCH, 512>>>((const float*)p_init, 1, ln_g, ln_b, intrinsic, threshold);

    // steps 1..11
    for (int s = 1; s < NSTEPS; ++s) {
        gemm_mma_kernel<<<dim3(NNEU / 64, 2), GEMM_THREADS, SMEM_DYN>>>(
            (const __nv_bfloat16*)p_ahi, (const __nv_bfloat16*)p_alo,
            (const __nv_bfloat16*)p_bhi, (const __nv_bfloat16*)p_blo, nullptr, (float*)p_total,
            NNEU);
        step_kernel<<<BATCH, 512>>>((const float*)p_total, 0, ln_g, ln_b, intrinsic, threshold);
    }

    cls_kernel<<<BATCH, 320>>>(cls_w, cls_b, out);
}